// round 15
// baseline (speedup 1.0000x reference)
#include <cuda_runtime.h>
#include <math.h>

// out[row] = tanh(sqrt(sum_j (w[row][j] - x[j])^2)), row in [0, 1048576), j in [0, 256)
//
// FINAL CHAMPION (R13/R14). HBM-roofline-bound: 1.074 GB read-once weight
// stream at 7.25-7.27 TB/s. Best ncu-internal durations of the session
// (148.45 / 148.96us) both belong to this kernel; bench reads ~2.7us higher
// (harness overhead) in a 150-152us weather band.
//
// Structure: warp handles TWO rows via 4 independent front-batched 128-bit
// evict-first streaming loads (each a fully-coalesced 512B warp transaction);
// x L1-resident via __ldg; warp-shuffle butterfly reduction; hardware
// tanh.approx.f32 epilogue (rel-err ~2^-11 << 1e-3 budget; issue 42%->32%
// vs tanhf). 32 regs, occ ~80-82%.
//
// Probes exhausted across 14 rounds (all neutral/negative, each diagnosed):
// MLP 8 @32regs (ptxas staged loads), MLP 8 @48regs (occupancy traded 1:1),
// persistent grid + prefetch, block=512, packed float2 stores, smem-served x.
// Bytes are irreducible; LTS is not binding at NAT clock; the wall is HBM.

__device__ __forceinline__ float htanh(float v) {
    float r;
    asm("tanh.approx.f32 %0, %1;" : "=f"(r) : "f"(v));
    return r;
}

__global__ __launch_bounds__(256) void sonia_l2_tanh_kernel2h(
    const float* __restrict__ x,
    const float* __restrict__ w,
    float* __restrict__ out,
    int n_rows)
{
    const int warp_id = (blockIdx.x * blockDim.x + threadIdx.x) >> 5;
    const int lane    = threadIdx.x & 31;
    const int row0    = warp_id * 2;
    if (row0 >= n_rows) return;

    const float4* __restrict__ wr = reinterpret_cast<const float4*>(w) + (size_t)row0 * 64;
    const float4* __restrict__ xr = reinterpret_cast<const float4*>(x);

    // x is tiny and re-read by every warp: L1/L2 resident.
    const float4 x0 = __ldg(xr + lane);
    const float4 x1 = __ldg(xr + lane + 32);

    // 4 independent streaming loads (evict-first: pure pass-through data).
    const float4 a0 = __ldcs(wr + lane);
    const float4 a1 = __ldcs(wr + lane + 32);
    const float4 b0 = __ldcs(wr + lane + 64);
    const float4 b1 = __ldcs(wr + lane + 96);

    float d;
    float sa = 0.0f, sb = 0.0f;
    d = a0.x - x0.x; sa = fmaf(d, d, sa);
    d = a0.y - x0.y; sa = fmaf(d, d, sa);
    d = a0.z - x0.z; sa = fmaf(d, d, sa);
    d = a0.w - x0.w; sa = fmaf(d, d, sa);
    d = a1.x - x1.x; sa = fmaf(d, d, sa);
    d = a1.y - x1.y; sa = fmaf(d, d, sa);
    d = a1.z - x1.z; sa = fmaf(d, d, sa);
    d = a1.w - x1.w; sa = fmaf(d, d, sa);

    d = b0.x - x0.x; sb = fmaf(d, d, sb);
    d = b0.y - x0.y; sb = fmaf(d, d, sb);
    d = b0.z - x0.z; sb = fmaf(d, d, sb);
    d = b0.w - x0.w; sb = fmaf(d, d, sb);
    d = b1.x - x1.x; sb = fmaf(d, d, sb);
    d = b1.y - x1.y; sb = fmaf(d, d, sb);
    d = b1.z - x1.z; sb = fmaf(d, d, sb);
    d = b1.w - x1.w; sb = fmaf(d, d, sb);

    // Butterfly reduce both sums across the warp.
    #pragma unroll
    for (int off = 16; off > 0; off >>= 1) {
        sa += __shfl_xor_sync(0xFFFFFFFFu, sa, off);
        sb += __shfl_xor_sync(0xFFFFFFFFu, sb, off);
    }

    if (lane == 0) {
        out[row0]     = htanh(sqrtf(sa));
        if (row0 + 1 < n_rows)
            out[row0 + 1] = htanh(sqrtf(sb));
    }
}

extern "C" void kernel_launch(void* const* d_in, const int* in_sizes, int n_in,
                              void* d_out, int out_size)
{
    const float* x = (const float*)d_in[0];   // input  [1, 256]
    const float* w = (const float*)d_in[1];   // weight [out_size, 256]
    float* out     = (float*)d_out;

    const int n_rows = out_size;              // 1048576
    // 8 warps/block, 2 rows/warp -> 16 rows per block
    const int rows_per_block = 16;
    const int blocks = (n_rows + rows_per_block - 1) / rows_per_block;

    sonia_l2_tanh_kernel2h<<<blocks, 256>>>(x, w, out, n_rows);
}

// round 16
// speedup vs baseline: 1.0011x; 1.0011x over previous
#include <cuda_runtime.h>
#include <math.h>

// out[row] = tanh(sqrt(sum_j (w[row][j] - x[j])^2)), row in [0, 1048576), j in [0, 256)
//
// FINAL CHAMPION (R13+, held through R15). HBM-roofline-bound: 1.074 GB
// read-once weight stream at 7.1-7.27 TB/s (chip's effective ceiling for this
// pattern; 89-92% of spec across runs). Best ncu-internal 148.45us; bench
// band 150-152us (harness overhead + DVFS weather), verified over six
// identical-binary runs.
//
// Structure: warp handles TWO rows via 4 independent front-batched 128-bit
// evict-first streaming loads (each a fully-coalesced 512B warp transaction);
// x L1-resident via __ldg; warp-shuffle butterfly reduction; hardware
// tanh.approx.f32 epilogue (rel-err ~2^-11 << 1e-3 budget; issue 42%->32%
// vs tanhf). 32 regs, occ ~80%.
//
// Probes exhausted across 15 rounds (all neutral/negative, each diagnosed):
// MLP 8 @32regs (ptxas staged loads), MLP 8 @48regs (occupancy traded 1:1),
// persistent grid + prefetch, block=512, packed float2 stores, smem-served x.
// Bytes are irreducible; LTS is not binding at NAT clock; the wall is HBM.

__device__ __forceinline__ float htanh(float v) {
    float r;
    asm("tanh.approx.f32 %0, %1;" : "=f"(r) : "f"(v));
    return r;
}

__global__ __launch_bounds__(256) void sonia_l2_tanh_kernel2h(
    const float* __restrict__ x,
    const float* __restrict__ w,
    float* __restrict__ out,
    int n_rows)
{
    const int warp_id = (blockIdx.x * blockDim.x + threadIdx.x) >> 5;
    const int lane    = threadIdx.x & 31;
    const int row0    = warp_id * 2;
    if (row0 >= n_rows) return;

    const float4* __restrict__ wr = reinterpret_cast<const float4*>(w) + (size_t)row0 * 64;
    const float4* __restrict__ xr = reinterpret_cast<const float4*>(x);

    // x is tiny and re-read by every warp: L1/L2 resident.
    const float4 x0 = __ldg(xr + lane);
    const float4 x1 = __ldg(xr + lane + 32);

    // 4 independent streaming loads (evict-first: pure pass-through data).
    const float4 a0 = __ldcs(wr + lane);
    const float4 a1 = __ldcs(wr + lane + 32);
    const float4 b0 = __ldcs(wr + lane + 64);
    const float4 b1 = __ldcs(wr + lane + 96);

    float d;
    float sa = 0.0f, sb = 0.0f;
    d = a0.x - x0.x; sa = fmaf(d, d, sa);
    d = a0.y - x0.y; sa = fmaf(d, d, sa);
    d = a0.z - x0.z; sa = fmaf(d, d, sa);
    d = a0.w - x0.w; sa = fmaf(d, d, sa);
    d = a1.x - x1.x; sa = fmaf(d, d, sa);
    d = a1.y - x1.y; sa = fmaf(d, d, sa);
    d = a1.z - x1.z; sa = fmaf(d, d, sa);
    d = a1.w - x1.w; sa = fmaf(d, d, sa);

    d = b0.x - x0.x; sb = fmaf(d, d, sb);
    d = b0.y - x0.y; sb = fmaf(d, d, sb);
    d = b0.z - x0.z; sb = fmaf(d, d, sb);
    d = b0.w - x0.w; sb = fmaf(d, d, sb);
    d = b1.x - x1.x; sb = fmaf(d, d, sb);
    d = b1.y - x1.y; sb = fmaf(d, d, sb);
    d = b1.z - x1.z; sb = fmaf(d, d, sb);
    d = b1.w - x1.w; sb = fmaf(d, d, sb);

    // Butterfly reduce both sums across the warp.
    #pragma unroll
    for (int off = 16; off > 0; off >>= 1) {
        sa += __shfl_xor_sync(0xFFFFFFFFu, sa, off);
        sb += __shfl_xor_sync(0xFFFFFFFFu, sb, off);
    }

    if (lane == 0) {
        out[row0]     = htanh(sqrtf(sa));
        if (row0 + 1 < n_rows)
            out[row0 + 1] = htanh(sqrtf(sb));
    }
}

extern "C" void kernel_launch(void* const* d_in, const int* in_sizes, int n_in,
                              void* d_out, int out_size)
{
    const float* x = (const float*)d_in[0];   // input  [1, 256]
    const float* w = (const float*)d_in[1];   // weight [out_size, 256]
    float* out     = (float*)d_out;

    const int n_rows = out_size;              // 1048576
    // 8 warps/block, 2 rows/warp -> 16 rows per block
    const int rows_per_block = 16;
    const int blocks = (n_rows + rows_per_block - 1) / rows_per_block;

    sonia_l2_tanh_kernel2h<<<blocks, 256>>>(x, w, out, n_rows);
}